// round 17
// baseline (speedup 1.0000x reference)
#include <cuda_runtime.h>
#include <cstdint>

// 26 node coordinates (compile-time __constant__ init; no runtime copy)
__constant__ float2 c_nodes[26] = {
    {0.5454545454545454f, 0.76f}, {0.6022727272727273f, 0.76f},
    {0.5454545454545454f, 0.86f}, {0.6022727272727273f, 0.86f},
    {0.4772727272727273f, 0.76f}, {0.42045454545454547f, 0.76f},
    {0.42045454545454547f, 0.86f}, {0.4772727272727273f, 0.86f},
    {0.32954545454545453f, 0.808f}, {0.42045454545454547f, 0.48f},
    {0.4772727272727273f, 0.48f}, {0.4772727272727273f, 0.38f},
    {0.42045454545454547f, 0.38f}, {0.32954545454545453f, 0.428f},
    {0.5727272727272728f, 0.62f}, {0.7613636363636364f, 0.76f},
    {0.8181818181818182f, 0.76f}, {0.8181818181818182f, 0.86f},
    {0.7613636363636364f, 0.86f}, {0.7909090909090909f, 0.62f},
    {0.9431818181818182f, 0.76f}, {1.0f, 0.76f},
    {1.0f, 0.86f}, {0.9431818181818182f, 0.86f},
    {0.9727272727272728f, 0.62f}, {0.9727272727272728f, 1.0f}
};

// Output row = 136 float2:
//   c in [0,3)->x2[c]; [3,67)->e1[c-3]; [67,69)->x2[c-64];
//   [69,133)->e2[c-69]; [133,136)->x2[c-128]
// 4 rows = 544 float2 = 17 x 256B, iterated flat: every store iteration is a
// dense 256B-aligned burst; iteration geometry is constexpr (template<K>).
// Staging is WARP-LOCAL (one dense 256B LDG per warp into its private smem
// slice, __syncwarp only — no block barrier; warps fully decoupled).
// This round: identical warp-level code, 128-thread CTAs (16 rows, grid 16384)
// for another 2x finer scheduling granularity (R13 512->R16 256 gained 1.4us).

constexpr int THREADS = 128;         // 4 warps x 4 rows = 16 rows/block
constexpr int ROWS_PER_BLOCK = 16;

template<int K>
__device__ __forceinline__ void do_iter(
    int lane,
    const float2* __restrict__ e1a, const float2* __restrict__ e1b,
    const float2* __restrict__ e2a, const float2* __restrict__ e2b,
    const float2* __restrict__ xa,  const float2* __restrict__ xb,
    float2* __restrict__ olane)
{
    constexpr int gs = K * 32;
    constexpr int ra = gs / 136;
    constexpr int rb = (gs + 31) / 136;
    constexpr int ca = gs - 136 * ra;        // c of lane 0 on low side
    float2 v;
    if constexpr (ra == rb) {
        if constexpr (ca >= 3 && ca + 31 < 67) {
            v = e1a[ca - 3 + lane];                    // pure e1: LDG only
        } else if constexpr (ca >= 69 && ca + 31 < 133) {
            v = e2a[ca - 69 + lane];                   // pure e2: LDG only
        } else {
            int c = ca + lane;
            if (c < 3)        v = xa[c];
            else if (c < 67)  v = e1a[c - 3];
            else if (c < 69)  v = xa[c - 64];
            else if (c < 133) v = e2a[c - 69];
            else              v = xa[c - 128];
        }
    } else {
        constexpr int split = 136 * rb - gs;           // 8, 16 or 24
        constexpr int cb = gs - 136 * rb;              // negative
        bool hi = lane >= split;
        int c = (hi ? cb : ca) + lane;
        const float2* e1 = hi ? e1b : e1a;
        const float2* e2 = hi ? e2b : e2a;
        const float2* xr = hi ? xb : xa;
        if (c < 3)        v = xr[c];
        else if (c < 67)  v = e1[c - 3];
        else if (c < 69)  v = xr[c - 64];
        else if (c < 133) v = e2[c - 69];
        else              v = xr[c - 128];
    }
    __stcs(&olane[gs], v);
}

__global__ __launch_bounds__(THREADS) void pe_kernel(
    const float* __restrict__ x,
    const float* __restrict__ emb,
    float* __restrict__ out,
    int rows)
{
    __shared__ float2 sx2[THREADS];              // 32 float2 per warp slice

    int block_row0 = blockIdx.x * ROWS_PER_BLOCK;
    int t = threadIdx.x;
    int warp = t >> 5;
    int lane = t & 31;

    // Warp-local stage: each warp loads ITS OWN 4 rows (dense 256B LDG.64)
    sx2[t] = reinterpret_cast<const float2*>(x)[(size_t)block_row0 * 8 + t];
    __syncwarp();

    const float2* wx = sx2 + warp * 32;          // this warp's 4 rows (32 float2)

    bool active = lane < 26;
    float nx = 0.f, ny = 0.f, tx = -1.f, ty = -1.f;
    if (active) {
        float2 n = c_nodes[lane];
        nx = n.x; ny = n.y;
        tx = 0.01f + 1e-5f * fabsf(nx);
        ty = 0.01f + 1e-5f * fabsf(ny);
    }

    const float2* emb2 = reinterpret_cast<const float2*>(emb);

    // Ballots for 4 rows -> per-row emb pointers (uniform across warp)
    const float2* e1p[4];
    const float2* e2p[4];
    const float2* xp[4];
    #pragma unroll
    for (int rr = 0; rr < 4; rr++) {
        float2 pt1 = wx[rr * 8 + 2];             // floats 4,5 of row rr
        float2 pt2 = wx[rr * 8 + 4];             // floats 8,9
        bool m1 = active && (fabsf(pt1.x - nx) <= tx) && (fabsf(pt1.y - ny) <= ty);
        bool m2 = active && (fabsf(pt2.x - nx) <= tx) && (fabsf(pt2.y - ny) <= ty);
        int idx1 = __ffs(__ballot_sync(0xffffffffu, m1));  // 1-based == argmax+1
        int idx2 = __ffs(__ballot_sync(0xffffffffu, m2));
        e1p[rr] = emb2 + (size_t)idx1 * 64;
        e2p[rr] = emb2 + (size_t)idx2 * 64;
        xp[rr]  = wx + rr * 8;
    }

    float2* olane = reinterpret_cast<float2*>(out)
                  + (size_t)(block_row0 + warp * 4) * 136 + lane;

#define ITER(K) do_iter<K>(lane, \
        e1p[(K*32)/136], e1p[((K*32)+31)/136], \
        e2p[(K*32)/136], e2p[((K*32)+31)/136], \
        xp[(K*32)/136],  xp[((K*32)+31)/136],  olane)
    ITER(0);  ITER(1);  ITER(2);  ITER(3);  ITER(4);  ITER(5);
    ITER(6);  ITER(7);  ITER(8);  ITER(9);  ITER(10); ITER(11);
    ITER(12); ITER(13); ITER(14); ITER(15); ITER(16);
#undef ITER
}

extern "C" void kernel_launch(void* const* d_in, const int* in_sizes, int n_in,
                              void* d_out, int out_size)
{
    const float* x;
    const float* emb;
    int xsz;
    if (in_sizes[0] > in_sizes[1]) {
        x = (const float*)d_in[0]; emb = (const float*)d_in[1]; xsz = in_sizes[0];
    } else {
        x = (const float*)d_in[1]; emb = (const float*)d_in[0]; xsz = in_sizes[1];
    }
    int rows = xsz / 16;                                       // 262144
    int blocks = (rows + ROWS_PER_BLOCK - 1) / ROWS_PER_BLOCK; // 16384 (exact)
    pe_kernel<<<blocks, THREADS>>>(x, emb, (float*)d_out, rows);
}